// round 7
// baseline (speedup 1.0000x reference)
#include <cuda_runtime.h>
#include <cuda_bf16.h>

typedef unsigned long long ull;

#define BATCH 2
#define CDIM 48
#define QC 144
#define HWD 512
#define HW (HWD*HWD)          // 262144
#define HEADS 8
#define NBF 96                // features per head = 6*4*4
#define NPIX 16384            // h1*w1 = 128*128

// ---------------- scratch (device globals, allocation-free) ----------------
__device__ float g_q1[BATCH*QC*HW];          // pointwise conv output (302MB)
__device__ float g_q2[BATCH*QC*HW];          // depthwise conv output (302MB)
__device__ float g_gram[BATCH*HEADS*NBF*NBF];
__device__ float g_ssq[BATCH*HEADS*2*NBF];   // [bh][q/k][feature] sum of squares
__device__ float g_attn[BATCH*HEADS*NBF*NBF];
__device__ float g_pre[BATCH*HEADS*NBF*NPIX];// attn@v, blocks layout (201MB)

// ---------------- packed fp32x2 helpers ----------------
__device__ __forceinline__ ull fma2(ull a, ull b, ull c) {
    ull d; asm("fma.rn.f32x2 %0,%1,%2,%3;" : "=l"(d) : "l"(a), "l"(b), "l"(c)); return d;
}
__device__ __forceinline__ ull add2(ull a, ull b) {
    ull d; asm("add.rn.f32x2 %0,%1,%2;" : "=l"(d) : "l"(a), "l"(b)); return d;
}
__device__ __forceinline__ ull pack2(float lo, float hi) {
    ull r; asm("mov.b64 %0,{%1,%2};" : "=l"(r) : "f"(lo), "f"(hi)); return r;
}
__device__ __forceinline__ float2 unpack2(ull v) {
    float2 r; asm("mov.b64 {%0,%1},%2;" : "=f"(r.x), "=f"(r.y) : "l"(v)); return r;
}

// ---------------- K0: zero accumulators ----------------
__global__ void k_zero() {
    int i = blockIdx.x * 256 + threadIdx.x;
    if (i < BATCH*HEADS*NBF*NBF) g_gram[i] = 0.f;
    if (i < BATCH*HEADS*2*NBF)   g_ssq[i]  = 0.f;
}

// ---------------- K1: 1x1 conv 48->144, f32x2, 2 pixels/thread ----------------
// Two phases of 72 output channels so the packed weight table fits static smem.
__global__ __launch_bounds__(256) void k_pw(const float* __restrict__ x,
                                            const float* __restrict__ w) {
    __shared__ ull ws[72*48];   // {w,w} packed, 27648 B
    int tid = threadIdx.x;
    int b = blockIdx.y;
    int p = blockIdx.x * 512 + tid * 2;      // 2 consecutive pixels
    const float* xb = x + (size_t)b * CDIM * HW + p;
    ull xr[48];
    #pragma unroll
    for (int ic = 0; ic < 48; ic++) xr[ic] = *(const ull*)(xb + ic * HW);
    float* ob = g_q1 + (size_t)b * QC * HW + p;

    for (int g = 0; g < 2; g++) {
        __syncthreads();
        for (int i = tid; i < 72*48; i += 256) {
            float v = w[g*72*48 + i];
            ws[i] = pack2(v, v);
        }
        __syncthreads();
        for (int oc = 0; oc < 72; oc++) {
            const ull* wr = ws + oc * 48;
            ull a0 = 0, a1 = 0, a2 = 0, a3 = 0;
            #pragma unroll
            for (int ic = 0; ic < 48; ic += 4) {
                a0 = fma2(wr[ic+0], xr[ic+0], a0);
                a1 = fma2(wr[ic+1], xr[ic+1], a1);
                a2 = fma2(wr[ic+2], xr[ic+2], a2);
                a3 = fma2(wr[ic+3], xr[ic+3], a3);
            }
            *(ull*)(ob + (size_t)(g*72 + oc) * HW) = add2(add2(a0, a1), add2(a2, a3));
        }
    }
}

// ---------------- K2: depthwise 3x3 (zero pad) + q/k row sum-of-squares ----------------
// One block = one (b,ch,h) row; thread handles pixels (2*tid, 2*tid+1).
__global__ __launch_bounds__(256) void k_dw(const float* __restrict__ dww) {
    int blk = blockIdx.x;          // b*144*512 + ch*512 + h
    int h  = blk & 511;
    int bc = blk >> 9;             // b*144 + ch
    int ch = bc % QC;
    int tid = threadIdx.x;
    int w = tid * 2;
    const float* base = g_q1 + (size_t)bc * HW;
    float wt[9];
    #pragma unroll
    for (int k = 0; k < 9; k++) wt[k] = __ldg(&dww[ch*9 + k]);
    float a0 = 0.f, a1 = 0.f;
    #pragma unroll
    for (int dy = 0; dy < 3; dy++) {
        int hh = h + dy - 1;
        if (hh < 0 || hh > 511) continue;
        const float* row = base + hh * 512 + w;
        float vm = (w > 0)   ? row[-1] : 0.f;
        float v0 = row[0];
        float v1 = row[1];
        float v2 = (w < 510) ? row[2] : 0.f;
        a0 += wt[dy*3+0]*vm + wt[dy*3+1]*v0 + wt[dy*3+2]*v1;
        a1 += wt[dy*3+0]*v0 + wt[dy*3+1]*v1 + wt[dy*3+2]*v2;
    }
    float2 o; o.x = a0; o.y = a1;
    *(float2*)(g_q2 + (size_t)bc * HW + h * 512 + w) = o;

    // Fused norm accumulation for q (ch<48) and k (48<=ch<96).
    if (ch < 96) {
        int qk = ch / 48, c48 = ch % 48;
        int head = c48 / 6, ci = c48 % 6;
        int b = bc / QC;
        int nh = h & 3;
        float s0 = a0 * a0, s1 = a1 * a1;   // s0: nw = 2*(lane&1), s1: nw+1
        #pragma unroll
        for (int off = 2; off < 32; off <<= 1) {
            s0 += __shfl_xor_sync(0xffffffffu, s0, off);
            s1 += __shfl_xor_sync(0xffffffffu, s1, off);
        }
        int lane = tid & 31;
        if (lane < 2) {
            int nw0 = lane * 2;             // lane0 -> nw {0,1}, lane1 -> nw {2,3}
            float* dst = &g_ssq[(((b*HEADS + head)*2) + qk) * NBF + (ci*4 + nh)*4];
            atomicAdd(&dst[nw0 + 0], s0);
            atomicAdd(&dst[nw0 + 1], s1);
        }
    }
}

// ---------------- K3: partial Gram q.kT per (bh, 512-pixel chunk) ----------------
// block (256 threads as 16x16): thread computes 6x6 output tile, f32x2 over pixel pairs.
__global__ __launch_bounds__(256) void k_gram() {
    __shared__ __align__(16) float qs[96*18];
    __shared__ __align__(16) float ks[96*18];
    int tid = threadIdx.x;
    int ty = tid >> 4, tx = tid & 15;
    int bh = blockIdx.y;
    int b = bh >> 3, head = bh & 7;
    int chunk = blockIdx.x;               // 0..31, 512 pixels each
    const float* src = g_q2 + (size_t)b * QC * HW;

    ull acc[6][6];
    #pragma unroll
    for (int i = 0; i < 6; i++)
        #pragma unroll
        for (int j = 0; j < 6; j++) acc[i][j] = 0ull;

    for (int sub = 0; sub < 32; sub++) {
        int s0 = chunk * 512 + sub * 16;
        __syncthreads();
        for (int e = tid; e < 1536; e += 256) {
            int r = e >> 4, c = e & 15;
            int s = s0 + c;
            int hh = ((s >> 7) << 2) + ((r >> 2) & 3);
            int ww = ((s & 127) << 2) + (r & 3);
            int chq = head * 6 + (r >> 4);
            int pix = hh * 512 + ww;
            qs[r*18 + c] = src[chq * HW + pix];
            ks[r*18 + c] = src[(chq + 48) * HW + pix];
        }
        __syncthreads();
        #pragma unroll
        for (int c = 0; c < 16; c += 2) {
            ull q2v[6], k2v[6];
            #pragma unroll
            for (int i = 0; i < 6; i++) q2v[i] = *(const ull*)&qs[(ty*6 + i)*18 + c];
            #pragma unroll
            for (int j = 0; j < 6; j++) k2v[j] = *(const ull*)&ks[(tx*6 + j)*18 + c];
            #pragma unroll
            for (int i = 0; i < 6; i++)
                #pragma unroll
                for (int j = 0; j < 6; j++)
                    acc[i][j] = fma2(q2v[i], k2v[j], acc[i][j]);
        }
    }
    #pragma unroll
    for (int i = 0; i < 6; i++)
        #pragma unroll
        for (int j = 0; j < 6; j++) {
            float2 u = unpack2(acc[i][j]);
            atomicAdd(&g_gram[(bh*NBF + ty*6 + i)*NBF + tx*6 + j], u.x + u.y);
        }
}

// ---------------- K4: normalize + temperature + softmax (1 warp / row) ----------------
__global__ __launch_bounds__(256) void k_soft(const float* __restrict__ temp) {
    int wid = threadIdx.x >> 5, lane = threadIdx.x & 31;
    int rid = blockIdx.x * 8 + wid;         // 0..1535
    int bh = rid / NBF, i = rid % NBF;
    int head = bh & 7;
    const float* ss = g_ssq + bh * 2 * NBF;
    float nq = fmaxf(sqrtf(ss[i]), 1e-12f);
    float t = temp[head];
    float v[3];
    #pragma unroll
    for (int u = 0; u < 3; u++) {
        int j = lane + 32*u;
        float nk = fmaxf(sqrtf(ss[NBF + j]), 1e-12f);
        v[u] = g_gram[(bh*NBF + i)*NBF + j] / (nq * nk) * t;
    }
    float m = fmaxf(v[0], fmaxf(v[1], v[2]));
    #pragma unroll
    for (int off = 16; off; off >>= 1) m = fmaxf(m, __shfl_xor_sync(0xffffffffu, m, off));
    float s = 0.f;
    #pragma unroll
    for (int u = 0; u < 3; u++) { v[u] = expf(v[u] - m); s += v[u]; }
    #pragma unroll
    for (int off = 16; off; off >>= 1) s += __shfl_xor_sync(0xffffffffu, s, off);
    float inv = 1.f / s;
    #pragma unroll
    for (int u = 0; u < 3; u++)
        g_attn[(bh*NBF + i)*NBF + lane + 32*u] = v[u] * inv;
}

// ---------------- K5: out = attn @ v, blocks layout output ----------------
// block (16x16): ty -> 6 rows, tx -> 4 pixels. attn packed {a,a} in smem, v gathered.
__global__ __launch_bounds__(256) void k_av() {
    __shared__ ull att_s[96*17];                  // per j-tile, {a,a}
    __shared__ __align__(16) float v_s[16*66];    // [16 j][64 px] (ull-padded rows)
    int tid = threadIdx.x;
    int ty = tid >> 4, tx = tid & 15;
    int bh = blockIdx.y;
    int b = bh >> 3, head = bh & 7;
    int s0 = blockIdx.x * 64;
    const float* src = g_q2 + (size_t)b * QC * HW;

    ull acc[6][2];
    #pragma unroll
    for (int i = 0; i < 6; i++) { acc[i][0] = 0ull; acc[i][1] = 0ull; }

    for (int jt = 0; jt < 6; jt++) {
        __syncthreads();
        for (int e = tid; e < 1536; e += 256) {     // attn tile 96x16
            int i = e >> 4, jj = e & 15;
            float a = g_attn[(bh*NBF + i)*NBF + jt*16 + jj];
            att_s[i*17 + jj] = pack2(a, a);
        }
        for (int e = tid; e < 1024; e += 256) {     // v tile 16x64 (gather)
            int jj = e >> 6, ss = e & 63;
            int j = jt*16 + jj;
            int s = s0 + ss;
            int hh = ((s >> 7) << 2) + ((j >> 2) & 3);
            int ww = ((s & 127) << 2) + (j & 3);
            int chv = 96 + head*6 + (j >> 4);
            v_s[jj*66 + ss] = src[chv * HW + hh*512 + ww];
        }
        __syncthreads();
        #pragma unroll
        for (int jc = 0; jc < 16; jc++) {
            ull v0 = *(const ull*)&v_s[jc*66 + tx*4];
            ull v1 = *(const ull*)&v_s[jc*66 + tx*4 + 2];
            #pragma unroll
            for (int i = 0; i < 6; i++) {
                ull a = att_s[(ty*6 + i)*17 + jc];
                acc[i][0] = fma2(a, v0, acc[i][0]);
                acc[i][1] = fma2(a, v1, acc[i][1]);
            }
        }
    }
    float* ob = g_pre + (size_t)bh * NBF * NPIX;
    #pragma unroll
    for (int i = 0; i < 6; i++) {
        int row = ty*6 + i;
        *(ull*)&ob[row*NPIX + s0 + tx*4]     = acc[i][0];
        *(ull*)&ob[row*NPIX + s0 + tx*4 + 2] = acc[i][1];
    }
}

// ---------------- K6: gather blocks + 1x1 proj -> d_out ----------------
// block (32x8): (b, h, 128-px w chunk). ty -> 6 oc, tx -> 4 pixels.
__global__ __launch_bounds__(256) void k_proj(const float* __restrict__ pw,
                                              float* __restrict__ out) {
    __shared__ ull w2s[48*48];                    // {w,w}, transposed [ic][oc]
    __shared__ __align__(16) float in_s[48*132];  // [ic][128 px]
    int tid = threadIdx.x + threadIdx.y * 32;
    int tx = threadIdx.x, ty = threadIdx.y;
    int wb = blockIdx.x * 128;
    int h = blockIdx.y;
    int b = blockIdx.z;
    int nh = h & 3;
    int sbase = (h >> 2) * 128;

    for (int e = tid; e < 2304; e += 256) {
        int oc = e / 48, ic = e % 48;
        float v = pw[e];                           // pw[oc*48+ic]
        w2s[ic*48 + oc] = pack2(v, v);
    }
    for (int e = tid; e < 48*128; e += 256) {
        int px = e & 127, ic = e >> 7;
        int head = ic / 6, ci = ic % 6;
        int w = wb + px;
        int f = (ci*4 + nh)*4 + (px & 3);
        int s = sbase + (w >> 2);
        in_s[ic*132 + px] = g_pre[((size_t)(b*HEADS + head)*NBF + f)*NPIX + s];
    }
    __syncthreads();

    ull acc[6][2];
    #pragma unroll
    for (int i = 0; i < 6; i++) { acc[i][0] = 0ull; acc[i][1] = 0ull; }
    #pragma unroll 4
    for (int ic = 0; ic < 48; ic++) {
        ull v0 = *(const ull*)&in_s[ic*132 + tx*4];
        ull v1 = *(const ull*)&in_s[ic*132 + tx*4 + 2];
        #pragma unroll
        for (int i = 0; i < 6; i++) {
            ull wv = w2s[ic*48 + ty*6 + i];
            acc[i][0] = fma2(wv, v0, acc[i][0]);
            acc[i][1] = fma2(wv, v1, acc[i][1]);
        }
    }
    #pragma unroll
    for (int i = 0; i < 6; i++) {
        int oc = ty*6 + i;
        float* ob = out + ((size_t)(b*CDIM + oc)*512 + h)*512 + wb + tx*4;
        *(ull*)&ob[0] = acc[i][0];
        *(ull*)&ob[2] = acc[i][1];
    }
}

extern "C" void kernel_launch(void* const* d_in, const int* in_sizes, int n_in,
                              void* d_out, int out_size) {
    const float* x     = (const float*)d_in[0];
    const float* qkvw  = (const float*)d_in[1];
    const float* dww   = (const float*)d_in[2];
    const float* projw = (const float*)d_in[3];
    const float* temp  = (const float*)d_in[4];
    float* out = (float*)d_out;

    k_zero<<<576, 256>>>();
    k_pw  <<<dim3(512, BATCH), 256>>>(x, qkvw);
    k_dw  <<<BATCH*QC*512, 256>>>(dww);
    k_gram<<<dim3(32, BATCH*HEADS), 256>>>();
    k_soft<<<192, 256>>>(temp);
    k_av  <<<dim3(256, BATCH*HEADS), 256>>>();
    k_proj<<<dim3(4, 512, BATCH), dim3(32, 8)>>>(projw, out);
}

// round 8
// speedup vs baseline: 1.2012x; 1.2012x over previous
#include <cuda_runtime.h>
#include <cuda_bf16.h>

typedef unsigned long long ull;

#define BATCH 2
#define CDIM 48
#define QC 144
#define HWD 512
#define HW (HWD*HWD)          // 262144
#define HEADS 8
#define NBF 96                // features per head = 6*4*4
#define NPIX 16384            // h1*w1 = 128*128

// ---------------- scratch (device globals, allocation-free) ----------------
__device__ float g_q1[BATCH*QC*HW];              // pointwise conv output (302MB)
__device__ float g_blk[BATCH*HEADS*3*NBF*NPIX];  // dw output, blocks layout (302MB)
__device__ float g_gram[BATCH*HEADS*NBF*NBF];
__device__ float g_ssq[BATCH*HEADS*2*NBF];       // [bh][q/k][feature] sum of squares
__device__ float g_attn[BATCH*HEADS*NBF*NBF];
__device__ float g_pre[BATCH*HEADS*NBF*NPIX];    // attn@v, blocks layout (201MB)

// ---------------- packed fp32x2 helpers ----------------
__device__ __forceinline__ ull fma2(ull a, ull b, ull c) {
    ull d; asm("fma.rn.f32x2 %0,%1,%2,%3;" : "=l"(d) : "l"(a), "l"(b), "l"(c)); return d;
}
__device__ __forceinline__ ull pack2(float lo, float hi) {
    ull r; asm("mov.b64 %0,{%1,%2};" : "=l"(r) : "f"(lo), "f"(hi)); return r;
}
__device__ __forceinline__ float2 unpack2(ull v) {
    float2 r; asm("mov.b64 {%0,%1},%2;" : "=f"(r.x), "=f"(r.y) : "l"(v)); return r;
}

// ---------------- K0: zero accumulators ----------------
__global__ void k_zero() {
    int i = blockIdx.x * 256 + threadIdx.x;
    if (i < BATCH*HEADS*NBF*NBF) g_gram[i] = 0.f;
    if (i < BATCH*HEADS*2*NBF)   g_ssq[i]  = 0.f;
}

// ---------------- K1: 1x1 conv 48->144, shared-tiled GEMM ----------------
// Block: 128 pixels x 144 oc (3 phases of 48 oc). tx(0..31)->4px, ty(0..7)->6oc.
__global__ __launch_bounds__(256) void k_pw(const float* __restrict__ x,
                                            const float* __restrict__ w) {
    __shared__ ull ws[48*48];                    // {w,w} packed, [ic][oc], 18KB
    __shared__ __align__(16) float xs[48*130];   // [ic][128px], 25KB
    int tid = threadIdx.x;
    int tx = tid & 31, ty = tid >> 5;
    int b = blockIdx.y;
    int px0 = blockIdx.x * 128;
    const float* xb = x + (size_t)b * CDIM * HW + px0;
    float* ob = g_q1 + (size_t)b * QC * HW + px0;

    for (int e = tid; e < 48*128; e += 256) {
        int ic = e >> 7, p = e & 127;
        xs[ic*130 + p] = xb[(size_t)ic * HW + p];
    }
    for (int g = 0; g < 3; g++) {
        __syncthreads();
        for (int e = tid; e < 48*48; e += 256) {
            int oc = e / 48, ic = e % 48;
            float v = w[g*48*48 + e];            // w[(g*48+oc)*48+ic]
            ws[ic*48 + oc] = pack2(v, v);
        }
        __syncthreads();
        ull acc[6][2];
        #pragma unroll
        for (int i = 0; i < 6; i++) { acc[i][0] = 0ull; acc[i][1] = 0ull; }
        #pragma unroll 4
        for (int ic = 0; ic < 48; ic++) {
            ull v0 = *(const ull*)&xs[ic*130 + tx*4];
            ull v1 = *(const ull*)&xs[ic*130 + tx*4 + 2];
            #pragma unroll
            for (int i = 0; i < 6; i++) {
                ull wv = ws[ic*48 + ty*6 + i];
                acc[i][0] = fma2(wv, v0, acc[i][0]);
                acc[i][1] = fma2(wv, v1, acc[i][1]);
            }
        }
        #pragma unroll
        for (int i = 0; i < 6; i++) {
            float* o = ob + (size_t)(g*48 + ty*6 + i) * HW + tx*4;
            *(ull*)&o[0] = acc[i][0];
            *(ull*)&o[2] = acc[i][1];
        }
    }
}

// ---------------- K2: depthwise 3x3 (zero pad), writes BLOCKS layout + ssq ----------------
// One block = one (b,ch,h) row; thread handles pixels (2*tid, 2*tid+1).
__global__ __launch_bounds__(256) void k_dw(const float* __restrict__ dww) {
    int blk = blockIdx.x;          // b*144*512 + ch*512 + h
    int h  = blk & 511;
    int bc = blk >> 9;             // b*144 + ch
    int ch = bc % QC;
    int b  = bc / QC;
    int tid = threadIdx.x;
    int w = tid * 2;
    const float* base = g_q1 + (size_t)bc * HW;
    float wt[9];
    #pragma unroll
    for (int k = 0; k < 9; k++) wt[k] = __ldg(&dww[ch*9 + k]);
    float a0 = 0.f, a1 = 0.f;
    #pragma unroll
    for (int dy = 0; dy < 3; dy++) {
        int hh = h + dy - 1;
        if (hh < 0 || hh > 511) continue;
        const float* row = base + hh * 512 + w;
        float vm = (w > 0)   ? row[-1] : 0.f;
        float v0 = row[0];
        float v1 = row[1];
        float v2 = (w < 510) ? row[2] : 0.f;
        a0 += wt[dy*3+0]*vm + wt[dy*3+1]*v0 + wt[dy*3+2]*v1;
        a1 += wt[dy*3+0]*v0 + wt[dy*3+1]*v1 + wt[dy*3+2]*v2;
    }
    // blocks layout write: f = (ci*4+nh)*4+nw, s = (h>>2)*128 + (w>>2)
    int qk = ch / 48, c48 = ch % 48;
    int head = c48 / 6, ci = c48 % 6;
    int nh = h & 3;
    int s = ((h >> 2) << 7) + (w >> 2);
    int f0 = (ci*4 + nh)*4 + (w & 3);
    float* dst = g_blk + ((size_t)((b*HEADS + head)*3 + qk) * NBF) * NPIX;
    dst[(size_t)f0 * NPIX + s]       = a0;
    dst[(size_t)(f0+1) * NPIX + s]   = a1;

    // Fused norm accumulation for q (qk=0) and k (qk=1).
    if (qk < 2) {
        float s0 = a0 * a0, s1 = a1 * a1;
        #pragma unroll
        for (int off = 2; off < 32; off <<= 1) {
            s0 += __shfl_xor_sync(0xffffffffu, s0, off);
            s1 += __shfl_xor_sync(0xffffffffu, s1, off);
        }
        int lane = tid & 31;
        if (lane < 2) {
            int nw0 = lane * 2;
            float* dstn = &g_ssq[(((b*HEADS + head)*2) + qk) * NBF + (ci*4 + nh)*4];
            atomicAdd(&dstn[nw0 + 0], s0);
            atomicAdd(&dstn[nw0 + 1], s1);
        }
    }
}

// ---------------- K3: partial Gram q.kT per (bh, 512-pixel chunk) ----------------
// Reads blocks layout rows (fully coalesced). 16x16 threads, 6x6 tile each.
__global__ __launch_bounds__(256, 2) void k_gram() {
    __shared__ __align__(16) float qs[96*34];
    __shared__ __align__(16) float ks[96*34];
    int tid = threadIdx.x;
    int ty = tid >> 4, tx = tid & 15;
    int bh = blockIdx.y;
    int chunk = blockIdx.x;               // 0..31, 512 pixels each
    const float* qb = g_blk + ((size_t)bh * 3 + 0) * NBF * NPIX;
    const float* kb = g_blk + ((size_t)bh * 3 + 1) * NBF * NPIX;

    ull acc[6][6];
    #pragma unroll
    for (int i = 0; i < 6; i++)
        #pragma unroll
        for (int j = 0; j < 6; j++) acc[i][j] = 0ull;

    for (int sub = 0; sub < 16; sub++) {
        int s0 = chunk * 512 + sub * 32;
        __syncthreads();
        for (int e = tid; e < 96*32; e += 256) {
            int r = e >> 5, c = e & 31;
            qs[r*34 + c] = qb[(size_t)r * NPIX + s0 + c];
            ks[r*34 + c] = kb[(size_t)r * NPIX + s0 + c];
        }
        __syncthreads();
        #pragma unroll
        for (int c = 0; c < 32; c += 2) {
            ull q2v[6], k2v[6];
            #pragma unroll
            for (int i = 0; i < 6; i++) q2v[i] = *(const ull*)&qs[(ty*6 + i)*34 + c];
            #pragma unroll
            for (int j = 0; j < 6; j++) k2v[j] = *(const ull*)&ks[(tx*6 + j)*34 + c];
            #pragma unroll
            for (int i = 0; i < 6; i++)
                #pragma unroll
                for (int j = 0; j < 6; j++)
                    acc[i][j] = fma2(q2v[i], k2v[j], acc[i][j]);
        }
    }
    #pragma unroll
    for (int i = 0; i < 6; i++)
        #pragma unroll
        for (int j = 0; j < 6; j++) {
            float2 u = unpack2(acc[i][j]);
            atomicAdd(&g_gram[(bh*NBF + ty*6 + i)*NBF + tx*6 + j], u.x + u.y);
        }
}

// ---------------- K4: normalize + temperature + softmax (1 warp / row) ----------------
__global__ __launch_bounds__(256) void k_soft(const float* __restrict__ temp) {
    int wid = threadIdx.x >> 5, lane = threadIdx.x & 31;
    int rid = blockIdx.x * 8 + wid;         // 0..1535
    int bh = rid / NBF, i = rid % NBF;
    int head = bh & 7;
    const float* ss = g_ssq + bh * 2 * NBF;
    float nq = fmaxf(sqrtf(ss[i]), 1e-12f);
    float t = temp[head];
    float v[3];
    #pragma unroll
    for (int u = 0; u < 3; u++) {
        int j = lane + 32*u;
        float nk = fmaxf(sqrtf(ss[NBF + j]), 1e-12f);
        v[u] = g_gram[(bh*NBF + i)*NBF + j] / (nq * nk) * t;
    }
    float m = fmaxf(v[0], fmaxf(v[1], v[2]));
    #pragma unroll
    for (int off = 16; off; off >>= 1) m = fmaxf(m, __shfl_xor_sync(0xffffffffu, m, off));
    float s = 0.f;
    #pragma unroll
    for (int u = 0; u < 3; u++) { v[u] = expf(v[u] - m); s += v[u]; }
    #pragma unroll
    for (int off = 16; off; off >>= 1) s += __shfl_xor_sync(0xffffffffu, s, off);
    float inv = 1.f / s;
    #pragma unroll
    for (int u = 0; u < 3; u++)
        g_attn[(bh*NBF + i)*NBF + lane + 32*u] = v[u] * inv;
}

// ---------------- K5: out = attn @ v, blocks layout in and out ----------------
// Block: 96 rows x 128 px. ty(0..15)->6 rows, tx(0..15)->8 px (4 ull). Low regs.
__global__ __launch_bounds__(256) void k_av() {
    __shared__ ull att_s[96*17];                  // per j-tile, {a,a}, 13KB
    __shared__ __align__(16) float v_s[16*132];   // [16 j][128 px], 8.4KB
    int tid = threadIdx.x;
    int ty = tid >> 4, tx = tid & 15;
    int bh = blockIdx.y;
    int px0 = blockIdx.x * 128;
    const float* vb = g_blk + ((size_t)bh * 3 + 2) * NBF * NPIX;

    ull acc[6][4];
    #pragma unroll
    for (int i = 0; i < 6; i++)
        #pragma unroll
        for (int u = 0; u < 4; u++) acc[i][u] = 0ull;

    for (int jt = 0; jt < 6; jt++) {
        __syncthreads();
        for (int e = tid; e < 1536; e += 256) {       // attn tile 96x16
            int i = e >> 4, jj = e & 15;
            float a = g_attn[(bh*NBF + i)*NBF + jt*16 + jj];
            att_s[i*17 + jj] = pack2(a, a);
        }
        for (int e = tid; e < 2048; e += 256) {       // v tile 16x128, coalesced rows
            int jj = e >> 7, p = e & 127;
            v_s[jj*132 + p] = vb[(size_t)(jt*16 + jj) * NPIX + px0 + p];
        }
        __syncthreads();
        #pragma unroll
        for (int jc = 0; jc < 16; jc++) {
            ull v0 = *(const ull*)&v_s[jc*132 + tx*8];
            ull v1 = *(const ull*)&v_s[jc*132 + tx*8 + 2];
            ull v2 = *(const ull*)&v_s[jc*132 + tx*8 + 4];
            ull v3 = *(const ull*)&v_s[jc*132 + tx*8 + 6];
            #pragma unroll
            for (int i = 0; i < 6; i++) {
                ull a = att_s[(ty*6 + i)*17 + jc];
                acc[i][0] = fma2(a, v0, acc[i][0]);
                acc[i][1] = fma2(a, v1, acc[i][1]);
                acc[i][2] = fma2(a, v2, acc[i][2]);
                acc[i][3] = fma2(a, v3, acc[i][3]);
            }
        }
    }
    float* ob = g_pre + (size_t)bh * NBF * NPIX;
    #pragma unroll
    for (int i = 0; i < 6; i++) {
        float* o = ob + (size_t)(ty*6 + i) * NPIX + px0 + tx*8;
        *(ull*)&o[0] = acc[i][0];
        *(ull*)&o[2] = acc[i][1];
        *(ull*)&o[4] = acc[i][2];
        *(ull*)&o[6] = acc[i][3];
    }
}

// ---------------- K6: gather blocks + 1x1 proj -> d_out ----------------
// block (32x8): (b, h, 128-px w chunk). ty -> 6 oc, tx -> 4 pixels.
__global__ __launch_bounds__(256) void k_proj(const float* __restrict__ pw,
                                              float* __restrict__ out) {
    __shared__ ull w2s[48*48];                    // {w,w}, transposed [ic][oc]
    __shared__ __align__(16) float in_s[48*132];  // [ic][128 px]
    int tid = threadIdx.x + threadIdx.y * 32;
    int tx = threadIdx.x, ty = threadIdx.y;
    int wb = blockIdx.x * 128;
    int h = blockIdx.y;
    int b = blockIdx.z;
    int nh = h & 3;
    int sbase = (h >> 2) * 128;

    for (int e = tid; e < 2304; e += 256) {
        int oc = e / 48, ic = e % 48;
        float v = pw[e];                           // pw[oc*48+ic]
        w2s[ic*48 + oc] = pack2(v, v);
    }
    for (int e = tid; e < 48*128; e += 256) {
        int px = e & 127, ic = e >> 7;
        int head = ic / 6, ci = ic % 6;
        int w = wb + px;
        int f = (ci*4 + nh)*4 + (px & 3);
        int s = sbase + (w >> 2);
        in_s[ic*132 + px] = g_pre[((size_t)(b*HEADS + head)*NBF + f)*NPIX + s];
    }
    __syncthreads();

    ull acc[6][2];
    #pragma unroll
    for (int i = 0; i < 6; i++) { acc[i][0] = 0ull; acc[i][1] = 0ull; }
    #pragma unroll 4
    for (int ic = 0; ic < 48; ic++) {
        ull v0 = *(const ull*)&in_s[ic*132 + tx*4];
        ull v1 = *(const ull*)&in_s[ic*132 + tx*4 + 2];
        #pragma unroll
        for (int i = 0; i < 6; i++) {
            ull wv = w2s[ic*48 + ty*6 + i];
            acc[i][0] = fma2(wv, v0, acc[i][0]);
            acc[i][1] = fma2(wv, v1, acc[i][1]);
        }
    }
    #pragma unroll
    for (int i = 0; i < 6; i++) {
        int oc = ty*6 + i;
        float* ob = out + ((size_t)(b*CDIM + oc)*512 + h)*512 + wb + tx*4;
        *(ull*)&ob[0] = acc[i][0];
        *(ull*)&ob[2] = acc[i][1];
    }
}

extern "C" void kernel_launch(void* const* d_in, const int* in_sizes, int n_in,
                              void* d_out, int out_size) {
    const float* x     = (const float*)d_in[0];
    const float* qkvw  = (const float*)d_in[1];
    const float* dww   = (const float*)d_in[2];
    const float* projw = (const float*)d_in[3];
    const float* temp  = (const float*)d_in[4];
    float* out = (float*)d_out;

    k_zero<<<576, 256>>>();
    k_pw  <<<dim3(HW/128, BATCH), 256>>>(x, qkvw);
    k_dw  <<<BATCH*QC*512, 256>>>(dww);
    k_gram<<<dim3(32, BATCH*HEADS), 256>>>();
    k_soft<<<192, 256>>>(temp);
    k_av  <<<dim3(NPIX/128, BATCH*HEADS), 256>>>();
    k_proj<<<dim3(4, 512, BATCH), dim3(32, 8)>>>(projw, out);
}

// round 11
// speedup vs baseline: 2.0488x; 1.7056x over previous
#include <cuda_runtime.h>
#include <cuda_bf16.h>
#include <cstdint>

typedef unsigned long long ull;
typedef unsigned int u32;

#define BATCH 2
#define CDIM 48
#define QC 144
#define HWD 512
#define HW (HWD*HWD)          // 262144
#define HEADS 8
#define NBF 96
#define NPIX 16384            // 128*128

// ---------------- scratch (aligned for cp.async / vector access) ----------------
__device__ __align__(128) float g_q1[BATCH*QC*HW];              // pw output
__device__ __align__(128) float g_blk[BATCH*HEADS*3*NBF*NPIX];  // dw out, blocks layout
__device__ __align__(128) float g_gram[BATCH*HEADS*NBF*NBF];
__device__ __align__(128) float g_ssq[BATCH*HEADS*2*NBF];
__device__ __align__(128) float g_attn[BATCH*HEADS*NBF*NBF];
__device__ __align__(128) float g_pre[BATCH*HEADS*NBF*NPIX];    // proj layout

// ---------------- helpers ----------------
__device__ __forceinline__ ull fma2(ull a, ull b, ull c) {
    ull d; asm("fma.rn.f32x2 %0,%1,%2,%3;" : "=l"(d) : "l"(a), "l"(b), "l"(c)); return d;
}
__device__ __forceinline__ ull pack2(float lo, float hi) {
    ull r; asm("mov.b64 %0,{%1,%2};" : "=l"(r) : "f"(lo), "f"(hi)); return r;
}
__device__ __forceinline__ float2 unpack2(ull v) {
    float2 r; asm("mov.b64 {%0,%1},%2;" : "=f"(r.x), "=f"(r.y) : "l"(v)); return r;
}
__device__ __forceinline__ void cp_async8(u32 dst, const void* src) {
    asm volatile("cp.async.ca.shared.global [%0], [%1], 8;" :: "r"(dst), "l"(src));
}
__device__ __forceinline__ void cp_async16(u32 dst, const void* src) {
    asm volatile("cp.async.cg.shared.global [%0], [%1], 16;" :: "r"(dst), "l"(src));
}
__device__ __forceinline__ void cp_commit() { asm volatile("cp.async.commit_group;"); }
__device__ __forceinline__ void cp_wait1() { asm volatile("cp.async.wait_group 1;"); }
__device__ __forceinline__ void cp_wait0() { asm volatile("cp.async.wait_group 0;"); }

// ---------------- K0 ----------------
__global__ void k_zero() {
    int i = blockIdx.x * 256 + threadIdx.x;
    if (i < BATCH*HEADS*NBF*NBF) g_gram[i] = 0.f;
    if (i < BATCH*HEADS*2*NBF)   g_ssq[i]  = 0.f;
}

// ---------------- K1: 1x1 conv 48->144 ----------------
__global__ __launch_bounds__(256) void k_pw(const float* __restrict__ x,
                                            const float* __restrict__ w) {
    __shared__ ull ws[48*48];                    // {w,w} [ic][oc]
    __shared__ __align__(16) float xs[48*130];
    int tid = threadIdx.x;
    int tx = tid & 31, ty = tid >> 5;
    int b = blockIdx.y;
    int px0 = blockIdx.x * 128;
    const float* xb = x + (size_t)b * CDIM * HW + px0;
    float* ob = g_q1 + (size_t)b * QC * HW + px0;

    for (int e = tid; e < 48*128; e += 256) {
        int ic = e >> 7, p = e & 127;
        xs[ic*130 + p] = xb[(size_t)ic * HW + p];
    }
    for (int g = 0; g < 3; g++) {
        __syncthreads();
        for (int e = tid; e < 48*48; e += 256) {
            int oc = e / 48, ic = e % 48;
            float v = w[g*48*48 + e];
            ws[ic*48 + oc] = pack2(v, v);
        }
        __syncthreads();
        ull acc[6][2];
        #pragma unroll
        for (int i = 0; i < 6; i++) { acc[i][0] = 0ull; acc[i][1] = 0ull; }
        #pragma unroll 4
        for (int ic = 0; ic < 48; ic++) {
            ull v0 = *(const ull*)&xs[ic*130 + 2*tx];
            ull v1 = *(const ull*)&xs[ic*130 + 64 + 2*tx];
            #pragma unroll
            for (int i = 0; i < 6; i++) {
                ull wv = ws[ic*48 + ty*6 + i];
                acc[i][0] = fma2(wv, v0, acc[i][0]);
                acc[i][1] = fma2(wv, v1, acc[i][1]);
            }
        }
        #pragma unroll
        for (int i = 0; i < 6; i++) {
            float* o = ob + (size_t)(g*48 + ty*6 + i) * HW;
            *(ull*)&o[2*tx]      = acc[i][0];
            *(ull*)&o[64 + 2*tx] = acc[i][1];
        }
    }
}

// ---------------- K2: depthwise 3x3, slab blocks, coalesced blocked writes + ssq ----------------
__global__ __launch_bounds__(256) void k_dw(const float* __restrict__ dww) {
    __shared__ __align__(16) float in_s[10*512];
    __shared__ __align__(16) float out_s[8*512];
    int blk = blockIdx.x;
    int hs = blk & 63;
    int bc = blk >> 6;
    int ch = bc % QC, b = bc / QC;
    int qk = ch / 48, c48 = ch % 48, head = c48 / 6, ci = c48 % 6;
    int tid = threadIdx.x;
    const float* base = g_q1 + (size_t)bc * HW;
    float wt[9];
    #pragma unroll
    for (int k = 0; k < 9; k++) wt[k] = __ldg(&dww[ch*9 + k]);
    int h0 = hs * 8;

    for (int e = tid; e < 5120; e += 256) {
        int rr = e >> 9, c = e & 511;
        int hh = h0 - 1 + rr;
        in_s[e] = (hh >= 0 && hh < 512) ? base[hh*512 + c] : 0.f;
    }
    __syncthreads();

    int w = tid * 2;
    float lsq[4][2] = {{0.f,0.f},{0.f,0.f},{0.f,0.f},{0.f,0.f}};
    #pragma unroll
    for (int r = 0; r < 8; r++) {
        float a0 = 0.f, a1 = 0.f;
        #pragma unroll
        for (int dy = 0; dy < 3; dy++) {
            const float* row = &in_s[(r + dy) * 512];
            float vm = (w > 0)   ? row[w-1] : 0.f;
            float v0 = row[w];
            float v1 = row[w+1];
            float v2 = (w < 510) ? row[w+2] : 0.f;
            a0 += wt[dy*3+0]*vm + wt[dy*3+1]*v0 + wt[dy*3+2]*v1;
            a1 += wt[dy*3+0]*v0 + wt[dy*3+1]*v1 + wt[dy*3+2]*v2;
        }
        *(ull*)&out_s[r*512 + w] = pack2(a0, a1);
        if (qk < 2) { int nh = r & 3; lsq[nh][0] += a0*a0; lsq[nh][1] += a1*a1; }
    }
    __syncthreads();

    float* dstbase = g_blk + (size_t)((b*HEADS + head)*3 + qk) * NBF * NPIX;
    for (int e = tid; e < 4096; e += 256) {
        int r = e >> 9, nw = (e >> 7) & 3, i = e & 127;
        float v = out_s[r*512 + i*4 + nw];
        int f = (ci*4 + (r & 3))*4 + nw;
        int s = (hs*2 + (r >> 2))*128 + i;
        dstbase[(size_t)f * NPIX + s] = v;
    }

    if (qk < 2) {
        #pragma unroll
        for (int off = 2; off < 32; off <<= 1)
            #pragma unroll
            for (int nh = 0; nh < 4; nh++) {
                lsq[nh][0] += __shfl_xor_sync(0xffffffffu, lsq[nh][0], off);
                lsq[nh][1] += __shfl_xor_sync(0xffffffffu, lsq[nh][1], off);
            }
        int lane = tid & 31;
        if (lane < 2) {
            float* d = &g_ssq[((b*HEADS + head)*2 + qk)*NBF + ci*16];
            #pragma unroll
            for (int nh = 0; nh < 4; nh++) {
                atomicAdd(&d[nh*4 + lane*2 + 0], lsq[nh][0]);
                atomicAdd(&d[nh*4 + lane*2 + 1], lsq[nh][1]);
            }
        }
    }
}

// ---------------- K3: partial Gram, cp.async double-buffered ----------------
#define GPITCH 34
#define GSTG (96*GPITCH)
__global__ __launch_bounds__(256, 2) void k_gram() {
    extern __shared__ float smg[];
    float* qs = smg;                 // [2][96][34]
    float* ks = smg + 2*GSTG;
    int tid = threadIdx.x;
    int ty = tid >> 4, tx = tid & 15;
    int bh = blockIdx.y;
    int chunk = blockIdx.x;
    const float* qb = g_blk + (size_t)bh * 3 * NBF * NPIX;
    const float* kb = qb + (size_t)NBF * NPIX;
    u32 qs_u = (u32)__cvta_generic_to_shared(qs);
    u32 ks_u = (u32)__cvta_generic_to_shared(ks);

    ull acc[6][6];
    #pragma unroll
    for (int i = 0; i < 6; i++)
        #pragma unroll
        for (int j = 0; j < 6; j++) acc[i][j] = 0ull;

    auto stage_copy = [&](int stg, int sub) {
        int s0 = chunk * 512 + sub * 32;
        for (int e = tid; e < 96*16; e += 256) {
            int r = e >> 4, c2 = (e & 15) * 2;
            u32 off = (u32)(stg*GSTG + r*GPITCH + c2) * 4;
            cp_async8(qs_u + off, qb + (size_t)r * NPIX + s0 + c2);
            cp_async8(ks_u + off, kb + (size_t)r * NPIX + s0 + c2);
        }
        cp_commit();
    };

    stage_copy(0, 0);
    for (int sub = 0; sub < 16; sub++) {
        int cur = sub & 1;
        if (sub < 15) { stage_copy(cur ^ 1, sub + 1); cp_wait1(); }
        else          { cp_wait0(); }
        __syncthreads();
        const float* q = qs + cur * GSTG;
        const float* k = ks + cur * GSTG;
        #pragma unroll
        for (int c = 0; c < 32; c += 2) {
            ull qv[6], kv[6];
            #pragma unroll
            for (int i = 0; i < 6; i++) qv[i] = *(const ull*)&q[(i*16 + ty)*GPITCH + c];
            #pragma unroll
            for (int j = 0; j < 6; j++) kv[j] = *(const ull*)&k[(j*16 + tx)*GPITCH + c];
            #pragma unroll
            for (int i = 0; i < 6; i++)
                #pragma unroll
                for (int j = 0; j < 6; j++)
                    acc[i][j] = fma2(qv[i], kv[j], acc[i][j]);
        }
        __syncthreads();
    }
    #pragma unroll
    for (int i = 0; i < 6; i++)
        #pragma unroll
        for (int j = 0; j < 6; j++) {
            float2 u = unpack2(acc[i][j]);
            atomicAdd(&g_gram[(bh*NBF + i*16 + ty)*NBF + j*16 + tx], u.x + u.y);
        }
}

// ---------------- K4: softmax ----------------
__global__ __launch_bounds__(256) void k_soft(const float* __restrict__ temp) {
    int wid = threadIdx.x >> 5, lane = threadIdx.x & 31;
    int rid = blockIdx.x * 8 + wid;
    int bh = rid / NBF, i = rid % NBF;
    int head = bh & 7;
    const float* ss = g_ssq + bh * 2 * NBF;
    float nq = fmaxf(sqrtf(ss[i]), 1e-12f);
    float t = temp[head];
    float v[3];
    #pragma unroll
    for (int u = 0; u < 3; u++) {
        int j = lane + 32*u;
        float nk = fmaxf(sqrtf(ss[NBF + j]), 1e-12f);
        v[u] = g_gram[(bh*NBF + i)*NBF + j] / (nq * nk) * t;
    }
    float m = fmaxf(v[0], fmaxf(v[1], v[2]));
    #pragma unroll
    for (int off = 16; off; off >>= 1) m = fmaxf(m, __shfl_xor_sync(0xffffffffu, m, off));
    float s = 0.f;
    #pragma unroll
    for (int u = 0; u < 3; u++) { v[u] = expf(v[u] - m); s += v[u]; }
    #pragma unroll
    for (int off = 16; off; off >>= 1) s += __shfl_xor_sync(0xffffffffu, s, off);
    float inv = 1.f / s;
    #pragma unroll
    for (int u = 0; u < 3; u++)
        g_attn[(bh*NBF + i)*NBF + lane + 32*u] = v[u] * inv;
}

// ---------------- K5: attn@v with async v tiles, output to proj layout ----------------
#define AV_VS_FLOATS (16*132)
__global__ __launch_bounds__(256, 2) void k_av() {
    extern __shared__ float sma[];
    float* att = sma;                         // [96][96]
    float* vs  = sma + 96*96;                 // [2][16][132]
    float* outs = sma;                        // [96][130] overlay (post-compute)
    int tid = threadIdx.x;
    int ty = tid >> 4, tx = tid & 15;
    int bh = blockIdx.y;
    int px0 = blockIdx.x * 128;
    const float* vb = g_blk + ((size_t)bh * 3 + 2) * NBF * NPIX;
    u32 vs_u = (u32)__cvta_generic_to_shared(vs);

    for (int e = tid; e < 96*96; e += 256) att[e] = g_attn[bh*NBF*NBF + e];

    ull acc[6][4];
    #pragma unroll
    for (int i = 0; i < 6; i++)
        #pragma unroll
        for (int u = 0; u < 4; u++) acc[i][u] = 0ull;

    auto vcopy = [&](int stg, int jt) {
        for (int e = tid; e < 512; e += 256) {
            int jc = e >> 5, ch = e & 31;
            u32 off = (u32)(stg*AV_VS_FLOATS + jc*132 + ch*4) * 4;
            cp_async16(vs_u + off, vb + (size_t)(jt*16 + jc) * NPIX + px0 + ch*4);
        }
        cp_commit();
    };

    vcopy(0, 0);
    __syncthreads();
    for (int jt = 0; jt < 6; jt++) {
        int cur = jt & 1;
        if (jt < 5) { vcopy(cur ^ 1, jt + 1); cp_wait1(); }
        else        { cp_wait0(); }
        __syncthreads();
        const float* vloc = vs + cur * AV_VS_FLOATS;
        #pragma unroll 2
        for (int jc = 0; jc < 16; jc++) {
            ull vv[4];
            #pragma unroll
            for (int u = 0; u < 4; u++) vv[u] = *(const ull*)&vloc[jc*132 + u*32 + 2*tx];
            #pragma unroll
            for (int i = 0; i < 6; i++) {
                float a = att[(ty*6 + i)*96 + jt*16 + jc];
                ull a2 = pack2(a, a);
                acc[i][0] = fma2(a2, vv[0], acc[i][0]);
                acc[i][1] = fma2(a2, vv[1], acc[i][1]);
                acc[i][2] = fma2(a2, vv[2], acc[i][2]);
                acc[i][3] = fma2(a2, vv[3], acc[i][3]);
            }
        }
        __syncthreads();
    }
    #pragma unroll
    for (int i = 0; i < 6; i++) {
        int row = ty*6 + i;
        #pragma unroll
        for (int u = 0; u < 4; u++)
            *(ull*)&outs[row*130 + u*32 + 2*tx] = acc[i][u];
    }
    __syncthreads();
    float* dst = g_pre + (size_t)bh * 24 * NPIX * 4 + (size_t)px0 * 4;
    for (int e = tid; e < 96*128; e += 256) {
        int p = e >> 9, l = e & 511;
        dst[(size_t)p * NPIX * 4 + l] = outs[(p*4 + (l & 3))*130 + (l >> 2)];
    }
}

// ---------------- K6: 1x1 proj -> d_out ----------------
__global__ __launch_bounds__(256) void k_proj(const float* __restrict__ pw,
                                              float* __restrict__ out) {
    __shared__ ull w2s[48*48];
    __shared__ __align__(16) float in_s[48*132];
    int tid = threadIdx.x + threadIdx.y * 32;
    int tx = threadIdx.x, ty = threadIdx.y;
    int wb = blockIdx.x * 128;
    int h = blockIdx.y;
    int b = blockIdx.z;
    int nh = h & 3;
    int soff = ((h >> 2) * 128 + (wb >> 2)) * 4;

    for (int e = tid; e < 2304; e += 256) {
        int oc = e / 48, ic = e % 48;
        float v = pw[e];
        w2s[ic*48 + oc] = pack2(v, v);
    }
    for (int e = tid; e < 48*128; e += 256) {
        int ic = e >> 7, px = e & 127;
        int head = ic / 6, ci = ic % 6;
        int p = ci*4 + nh;
        in_s[ic*132 + px] =
            g_pre[((size_t)(b*HEADS + head)*24 + p) * NPIX * 4 + soff + px];
    }
    __syncthreads();

    ull acc[6][2];
    #pragma unroll
    for (int i = 0; i < 6; i++) { acc[i][0] = 0ull; acc[i][1] = 0ull; }
    #pragma unroll 4
    for (int ic = 0; ic < 48; ic++) {
        ull v0 = *(const ull*)&in_s[ic*132 + 2*tx];
        ull v1 = *(const ull*)&in_s[ic*132 + 64 + 2*tx];
        #pragma unroll
        for (int i = 0; i < 6; i++) {
            ull wv = w2s[ic*48 + ty*6 + i];
            acc[i][0] = fma2(wv, v0, acc[i][0]);
            acc[i][1] = fma2(wv, v1, acc[i][1]);
        }
    }
    #pragma unroll
    for (int i = 0; i < 6; i++) {
        int oc = ty*6 + i;
        float* ob = out + ((size_t)(b*CDIM + oc)*512 + h)*512 + wb;
        *(ull*)&ob[2*tx]      = acc[i][0];
        *(ull*)&ob[64 + 2*tx] = acc[i][1];
    }
}

extern "C" void kernel_launch(void* const* d_in, const int* in_sizes, int n_in,
                              void* d_out, int out_size) {
    const float* x     = (const float*)d_in[0];
    const float* qkvw  = (const float*)d_in[1];
    const float* dww   = (const float*)d_in[2];
    const float* projw = (const float*)d_in[3];
    const float* temp  = (const float*)d_in[4];
    float* out = (float*)d_out;

    int gram_smem = 4 * GSTG * 4;                       // 52224 B
    int av_smem   = (96*96 + 2*AV_VS_FLOATS) * 4;       // 53760 B
    cudaFuncSetAttribute(k_gram, cudaFuncAttributeMaxDynamicSharedMemorySize, gram_smem);
    cudaFuncSetAttribute(k_av,   cudaFuncAttributeMaxDynamicSharedMemorySize, av_smem);

    k_zero<<<576, 256>>>();
    k_pw  <<<dim3(HW/128, BATCH), 256>>>(x, qkvw);
    k_dw  <<<BATCH*QC*64, 256>>>(dww);
    k_gram<<<dim3(32, BATCH*HEADS), 256, gram_smem>>>();
    k_soft<<<192, 256>>>(temp);
    k_av  <<<dim3(NPIX/128, BATCH*HEADS), 256, av_smem>>>();
    k_proj<<<dim3(4, 512, BATCH), dim3(32, 8)>>>(projw, out);
}

// round 14
// speedup vs baseline: 2.4533x; 1.1974x over previous
#include <cuda_runtime.h>
#include <cuda_bf16.h>
#include <cuda_fp16.h>
#include <cstdint>

typedef unsigned long long ull;
typedef unsigned int u32;

#define BATCH 2
#define CDIM 48
#define QC 144
#define HWD 512
#define HW (HWD*HWD)          // 262144
#define HEADS 8
#define NBH 16
#define NBF 96
#define NPIX 16384            // 128*128

// ---------------- scratch ----------------
__device__ __align__(128) __half g_q1[BATCH*QC*HW];             // pw output fp16
__device__ __align__(128) float  g_blk[NBH*3*NBF*NPIX];         // dw out q,k,v fp32 blocks
__device__ __align__(128) float  g_gram[NBH*NBF*NBF];
__device__ __align__(128) float  g_ssq[NBH*2*NBF];
__device__ __align__(128) float  g_attn[NBH*NBF*NBF];
__device__ __align__(128) __half g_pre16[NBH*NBF*NPIX];         // attn@v fp16, proj layout

// ---------------- helpers ----------------
__device__ __forceinline__ ull fma2(ull a, ull b, ull c) {
    ull d; asm("fma.rn.f32x2 %0,%1,%2,%3;" : "=l"(d) : "l"(a), "l"(b), "l"(c)); return d;
}
__device__ __forceinline__ ull pack2(float lo, float hi) {
    ull r; asm("mov.b64 %0,{%1,%2};" : "=l"(r) : "f"(lo), "f"(hi)); return r;
}
__device__ __forceinline__ float2 unpack2(ull v) {
    float2 r; asm("mov.b64 {%0,%1},%2;" : "=f"(r.x), "=f"(r.y) : "l"(v)); return r;
}
__device__ __forceinline__ u32 smem_u32(const void* p) {
    u32 a; asm("{ .reg .u64 t; cvta.to.shared.u64 t, %1; cvt.u32.u64 %0, t; }" : "=r"(a) : "l"(p));
    return a;
}
__device__ __forceinline__ void cp_async8(u32 dst, const void* src) {
    asm volatile("cp.async.ca.shared.global [%0], [%1], 8;" :: "r"(dst), "l"(src));
}
__device__ __forceinline__ void cp_async16(u32 dst, const void* src) {
    asm volatile("cp.async.cg.shared.global [%0], [%1], 16;" :: "r"(dst), "l"(src));
}
__device__ __forceinline__ void cp_commit() { asm volatile("cp.async.commit_group;"); }
__device__ __forceinline__ void cp_wait1() { asm volatile("cp.async.wait_group 1;"); }
__device__ __forceinline__ void cp_wait0() { asm volatile("cp.async.wait_group 0;"); }

// ---------------- K0: zero accumulators ----------------
__global__ void k_zero() {
    int i = blockIdx.x * 256 + threadIdx.x;
    if (i < NBH*NBF*NBF) g_gram[i] = 0.f;
    if (i < NBH*2*NBF)   g_ssq[i]  = 0.f;
}

// ---------------- K1: 1x1 conv 48->144, 256-px tile, fp16 out ----------------
#define PW_SMEM (48*48*8 + 48*260*4)   // 68352
__global__ __launch_bounds__(256) void k_pw(const float* __restrict__ x,
                                            const float* __restrict__ w) {
    extern __shared__ char spw[];
    ull*   ws = (ull*)spw;                      // {w,w} [ic][oc]
    float* xs = (float*)(spw + 48*48*8);        // [48][260]
    int tid = threadIdx.x;
    int tx = tid & 31, ty = tid >> 5;
    int b = blockIdx.y;
    int px0 = blockIdx.x * 256;
    const float* xb = x + (size_t)b * CDIM * HW + px0;
    __half* ob = g_q1 + (size_t)b * QC * HW + px0;
    u32 xs_u = smem_u32(xs);

    for (int e = tid; e < 48*64; e += 256) {
        int ic = e >> 6, p4 = (e & 63) * 4;
        cp_async16(xs_u + (u32)(ic*260 + p4) * 4, xb + (size_t)ic * HW + p4);
    }
    cp_commit();

    for (int g = 0; g < 3; g++) {
        if (g) __syncthreads();
        for (int e = tid; e < 48*48; e += 256) {
            int oc = e / 48, ic = e % 48;
            float v = w[g*2304 + e];
            ws[ic*48 + oc] = pack2(v, v);
        }
        if (g == 0) cp_wait0();
        __syncthreads();
        ull acc[6][4];
        #pragma unroll
        for (int i = 0; i < 6; i++)
            #pragma unroll
            for (int u = 0; u < 4; u++) acc[i][u] = 0ull;
        #pragma unroll 4
        for (int ic = 0; ic < 48; ic++) {
            float4 xa = *(const float4*)&xs[ic*260 + 4*tx];
            float4 xc = *(const float4*)&xs[ic*260 + 128 + 4*tx];
            ull a0 = pack2(xa.x, xa.y), a1 = pack2(xa.z, xa.w);
            ull a2 = pack2(xc.x, xc.y), a3 = pack2(xc.z, xc.w);
            #pragma unroll
            for (int i = 0; i < 6; i++) {
                ull wv = ws[ic*48 + ty*6 + i];
                acc[i][0] = fma2(wv, a0, acc[i][0]);
                acc[i][1] = fma2(wv, a1, acc[i][1]);
                acc[i][2] = fma2(wv, a2, acc[i][2]);
                acc[i][3] = fma2(wv, a3, acc[i][3]);
            }
        }
        #pragma unroll
        for (int i = 0; i < 6; i++) {
            __half* o = ob + (size_t)(g*48 + ty*6 + i) * HW;
            float2 f0 = unpack2(acc[i][0]), f1 = unpack2(acc[i][1]);
            float2 f2 = unpack2(acc[i][2]), f3 = unpack2(acc[i][3]);
            __half2 h0 = __floats2half2_rn(f0.x, f0.y), h1 = __floats2half2_rn(f1.x, f1.y);
            __half2 h2 = __floats2half2_rn(f2.x, f2.y), h3 = __floats2half2_rn(f3.x, f3.y);
            uint2 u01; u01.x = *(u32*)&h0; u01.y = *(u32*)&h1;
            uint2 u23; u23.x = *(u32*)&h2; u23.y = *(u32*)&h3;
            *(uint2*)&o[4*tx]       = u01;
            *(uint2*)&o[128 + 4*tx] = u23;
        }
    }
}

// ---------------- K2: depthwise 3x3 (fp16 in, fp32 blocks out) + ssq ----------------
__global__ __launch_bounds__(256) void k_dw(const float* __restrict__ dww) {
    __shared__ __align__(16) float in_s[10*512];
    __shared__ __align__(16) float out_s[8*512];
    int blk = blockIdx.x;
    int hs = blk & 63;
    int bc = blk >> 6;
    int ch = bc % QC, b = bc / QC;
    int qk = ch / 48, c48 = ch % 48, head = c48 / 6, ci = c48 % 6;
    int bhi = b*HEADS + head;
    int tid = threadIdx.x;
    const __half* base = g_q1 + (size_t)bc * HW;
    float wt[9];
    #pragma unroll
    for (int k = 0; k < 9; k++) wt[k] = __ldg(&dww[ch*9 + k]);
    int h0 = hs * 8;

    for (int e = tid; e < 2560; e += 256) {
        int rr = e >> 8, c2 = (e & 255) * 2;
        int hh = h0 - 1 + rr;
        float2 f;
        if (hh >= 0 && hh < 512) {
            __half2 hv = *(const __half2*)(base + (size_t)hh*512 + c2);
            f = __half22float2(hv);
        } else { f.x = 0.f; f.y = 0.f; }
        *(float2*)&in_s[rr*512 + c2] = f;
    }
    __syncthreads();

    int w = tid * 2;
    float lsq[4][2] = {{0.f,0.f},{0.f,0.f},{0.f,0.f},{0.f,0.f}};
    #pragma unroll
    for (int r = 0; r < 8; r++) {
        float a0 = 0.f, a1 = 0.f;
        #pragma unroll
        for (int dy = 0; dy < 3; dy++) {
            const float* row = &in_s[(r + dy) * 512];
            float vm = (w > 0)   ? row[w-1] : 0.f;
            float v0 = row[w];
            float v1 = row[w+1];
            float v2 = (w < 510) ? row[w+2] : 0.f;
            a0 += wt[dy*3+0]*vm + wt[dy*3+1]*v0 + wt[dy*3+2]*v1;
            a1 += wt[dy*3+0]*v0 + wt[dy*3+1]*v1 + wt[dy*3+2]*v2;
        }
        *(ull*)&out_s[r*512 + w] = pack2(a0, a1);
        if (qk < 2) { int nh = r & 3; lsq[nh][0] += a0*a0; lsq[nh][1] += a1*a1; }
    }
    __syncthreads();

    float* dstbase = g_blk + (size_t)(bhi*3 + qk) * NBF * NPIX;
    for (int e = tid; e < 4096; e += 256) {
        int r = e >> 9, nw = (e >> 7) & 3, i = e & 127;
        float v = out_s[r*512 + i*4 + nw];
        int f = (ci*4 + (r & 3))*4 + nw;
        int s = (hs*2 + (r >> 2))*128 + i;
        dstbase[(size_t)f * NPIX + s] = v;
    }

    if (qk < 2) {
        #pragma unroll
        for (int off = 2; off < 32; off <<= 1)
            #pragma unroll
            for (int nh = 0; nh < 4; nh++) {
                lsq[nh][0] += __shfl_xor_sync(0xffffffffu, lsq[nh][0], off);
                lsq[nh][1] += __shfl_xor_sync(0xffffffffu, lsq[nh][1], off);
            }
        int lane = tid & 31;
        if (lane < 2) {
            float* d = &g_ssq[(bhi*2 + qk)*NBF + ci*16];
            #pragma unroll
            for (int nh = 0; nh < 4; nh++) {
                atomicAdd(&d[nh*4 + lane*2 + 0], lsq[nh][0]);
                atomicAdd(&d[nh*4 + lane*2 + 1], lsq[nh][1]);
            }
        }
    }
}

// ---------------- K3: partial Gram, cp.async double-buffered (unchanged, fp32) ----------------
#define GPITCH 34
#define GSTG (96*GPITCH)
__global__ __launch_bounds__(256, 2) void k_gram() {
    extern __shared__ float smg[];
    float* qs = smg;                 // [2][96][34]
    float* ks = smg + 2*GSTG;
    int tid = threadIdx.x;
    int ty = tid >> 4, tx = tid & 15;
    int bh = blockIdx.y;
    int chunk = blockIdx.x;
    const float* qb = g_blk + (size_t)bh * 3 * NBF * NPIX;
    const float* kb = qb + (size_t)NBF * NPIX;
    u32 qs_u = smem_u32(qs);
    u32 ks_u = smem_u32(ks);

    ull acc[6][6];
    #pragma unroll
    for (int i = 0; i < 6; i++)
        #pragma unroll
        for (int j = 0; j < 6; j++) acc[i][j] = 0ull;

    auto stage_copy = [&](int stg, int sub) {
        int s0 = chunk * 512 + sub * 32;
        for (int e = tid; e < 96*16; e += 256) {
            int r = e >> 4, c2 = (e & 15) * 2;
            u32 off = (u32)(stg*GSTG + r*GPITCH + c2) * 4;
            cp_async8(qs_u + off, qb + (size_t)r * NPIX + s0 + c2);
            cp_async8(ks_u + off, kb + (size_t)r * NPIX + s0 + c2);
        }
        cp_commit();
    };

    stage_copy(0, 0);
    for (int sub = 0; sub < 16; sub++) {
        int cur = sub & 1;
        if (sub < 15) { stage_copy(cur ^ 1, sub + 1); cp_wait1(); }
        else          { cp_wait0(); }
        __syncthreads();
        const float* q = qs + cur * GSTG;
        const float* k = ks + cur * GSTG;
        #pragma unroll
        for (int c = 0; c < 32; c += 2) {
            ull qv[6], kv[6];
            #pragma unroll
            for (int i = 0; i < 6; i++) qv[i] = *(const ull*)&q[(i*16 + ty)*GPITCH + c];
            #pragma unroll
            for (int j = 0; j < 6; j++) kv[j] = *(const ull*)&k[(j*16 + tx)*GPITCH + c];
            #pragma unroll
            for (int i = 0; i < 6; i++)
                #pragma unroll
                for (int j = 0; j < 6; j++)
                    acc[i][j] = fma2(qv[i], kv[j], acc[i][j]);
        }
        __syncthreads();
    }
    #pragma unroll
    for (int i = 0; i < 6; i++)
        #pragma unroll
        for (int j = 0; j < 6; j++) {
            float2 u = unpack2(acc[i][j]);
            atomicAdd(&g_gram[(bh*NBF + i*16 + ty)*NBF + j*16 + tx], u.x + u.y);
        }
}

// ---------------- K4: softmax ----------------
__global__ __launch_bounds__(256) void k_soft(const float* __restrict__ temp) {
    int wid = threadIdx.x >> 5, lane = threadIdx.x & 31;
    int rid = blockIdx.x * 8 + wid;
    int bh = rid / NBF, i = rid % NBF;
    int head = bh & 7;
    const float* ss = g_ssq + bh * 2 * NBF;
    float nq = fmaxf(sqrtf(ss[i]), 1e-12f);
    float t = temp[head];
    float v[3];
    #pragma unroll
    for (int u = 0; u < 3; u++) {
        int j = lane + 32*u;
        float nk = fmaxf(sqrtf(ss[NBF + j]), 1e-12f);
        v[u] = g_gram[(bh*NBF + i)*NBF + j] / (nq * nk) * t;
    }
    float m = fmaxf(v[0], fmaxf(v[1], v[2]));
    #pragma unroll
    for (int off = 16; off; off >>= 1) m = fmaxf(m, __shfl_xor_sync(0xffffffffu, m, off));
    float s = 0.f;
    #pragma unroll
    for (int u = 0; u < 3; u++) { v[u] = expf(v[u] - m); s += v[u]; }
    #pragma unroll
    for (int off = 16; off; off >>= 1) s += __shfl_xor_sync(0xffffffffu, s, off);
    float inv = 1.f / s;
    #pragma unroll
    for (int u = 0; u < 3; u++)
        g_attn[(bh*NBF + i)*NBF + lane + 32*u] = v[u] * inv;
}

// ---------------- K5: attn@v, prepacked attn, fp16 output ----------------
#define AV_VS_FLOATS (16*132)
#define AV_SMEM (96*96*8 + 2*AV_VS_FLOATS*4)   // 90624
__global__ __launch_bounds__(256, 2) void k_av() {
    extern __shared__ char sma[];
    ull*   att  = (ull*)sma;                    // [96][96] packed {a,a}
    float* vs   = (float*)(sma + 96*96*8);      // [2][16][132]
    float* outs = (float*)sma;                  // [96][130] overlay (post-compute)
    int tid = threadIdx.x;
    int ty = tid >> 4, tx = tid & 15;
    int bh = blockIdx.y;
    int px0 = blockIdx.x * 128;
    const float* vb = g_blk + (size_t)(bh*3 + 2) * NBF * NPIX;
    u32 vs_u = smem_u32(vs);

    for (int e = tid; e < 96*96; e += 256) {
        float a = g_attn[bh*NBF*NBF + e];
        att[e] = pack2(a, a);
    }

    ull acc[6][4];
    #pragma unroll
    for (int i = 0; i < 6; i++)
        #pragma unroll
        for (int u = 0; u < 4; u++) acc[i][u] = 0ull;

    auto vcopy = [&](int stg, int jt) {
        for (int e = tid; e < 512; e += 256) {
            int jc = e >> 5, ch = e & 31;
            u32 off = (u32)(stg*AV_VS_FLOATS + jc*132 + ch*4) * 4;
            cp_async16(vs_u + off, vb + (size_t)(jt*16 + jc) * NPIX + px0 + ch*4);
        }
        cp_commit();
    };

    vcopy(0, 0);
    __syncthreads();
    for (int jt = 0; jt < 6; jt++) {
        int cur = jt & 1;
        if (jt < 5) { vcopy(cur ^ 1, jt + 1); cp_wait1(); }
        else        { cp_wait0(); }
        __syncthreads();
        const float* vloc = vs + cur * AV_VS_FLOATS;
        #pragma unroll 2
        for (int jc = 0; jc < 16; jc++) {
            ull vv[4];
            #pragma unroll
            for (int u = 0; u < 4; u++) vv[u] = *(const ull*)&vloc[jc*132 + u*32 + 2*tx];
            #pragma unroll
            for (int i = 0; i < 6; i++) {
                ull a2 = att[(ty*6 + i)*96 + jt*16 + jc];
                acc[i][0] = fma2(a2, vv[0], acc[i][0]);
                acc[i][1] = fma2(a2, vv[1], acc[i][1]);
                acc[i][2] = fma2(a2, vv[2], acc[i][2]);
                acc[i][3] = fma2(a2, vv[3], acc[i][3]);
            }
        }
        __syncthreads();
    }
    #pragma unroll
    for (int i = 0; i < 6; i++) {
        int row = ty*6 + i;
        #pragma unroll
        for (int u = 0; u < 4; u++)
            *(ull*)&outs[row*130 + u*32 + 2*tx] = acc[i][u];
    }
    __syncthreads();
    __half* dst = g_pre16 + (size_t)bh * 24 * NPIX * 4 + (size_t)px0 * 4;
    for (int e = tid; e < 24*256; e += 256) {
        int p = e >> 8, r = e & 255;
        int s = r >> 1, nwp = (r & 1) * 2;
        float f0 = outs[(p*4 + nwp    )*130 + s];
        float f1 = outs[(p*4 + nwp + 1)*130 + s];
        *(__half2*)&dst[(size_t)p * NPIX * 4 + s*4 + nwp] = __floats2half2_rn(f0, f1);
    }
}

// ---------------- K6: 1x1 proj (fp16 in), 256-px tile -> d_out ----------------
#define PROJ_SMEM (48*48*8 + 48*260*4)   // 68352
__global__ __launch_bounds__(256) void k_proj(const float* __restrict__ pw,
                                              float* __restrict__ out) {
    extern __shared__ char spj[];
    ull*   w2s  = (ull*)spj;
    float* in_s = (float*)(spj + 48*48*8);      // [48][260]
    int tid = threadIdx.x + threadIdx.y * 32;
    int tx = threadIdx.x, ty = threadIdx.y;
    int wb = blockIdx.x * 256;
    int h = blockIdx.y;
    int b = blockIdx.z;
    int nh = h & 3;
    int soff = ((h >> 2) * 128 + (wb >> 2)) * 4;

    for (int e = tid; e < 2304; e += 256) {
        int oc = e / 48, ic = e % 48;
        float v = pw[e];
        w2s[ic*48 + oc] = pack2(v, v);
    }
    for (int e = tid; e < 48*128; e += 256) {
        int ic = e >> 7, p2 = (e & 127) * 2;
        int head = ic / 6, ci = ic % 6;
        int p = ci*4 + nh;
        const __half* src = g_pre16 +
            ((size_t)(b*HEADS + head)*24 + p) * NPIX * 4 + soff + p2;
        float2 f = __half22float2(*(const __half2*)src);
        *(float2*)&in_s[ic*260 + p2] = f;
    }
    __syncthreads();

    ull acc[6][4];
    #pragma unroll
    for (int i = 0; i < 6; i++)
        #pragma unroll
        for (int u = 0; u < 4; u++) acc[i][u] = 0ull;
    #pragma unroll 4
    for (int ic = 0; ic < 48; ic++) {
        float4 xa = *(const float4*)&in_s[ic*260 + 4*tx];
        float4 xc = *(const float4*)&in_s[ic*260 + 128 + 4*tx];
        ull a0 = pack2(xa.x, xa.y), a1 = pack2(xa.z, xa.w);
        ull a2 = pack2(xc.x, xc.y), a3 = pack2(xc.z, xc.w);
        #pragma unroll
        for (int i = 0; i < 6; i++) {
            ull wv = w2s[ic*48 + ty*6 + i];
            acc[i][0] = fma2(wv, a0, acc[i][0]);
            acc[i][1] = fma2(wv, a1, acc[i][1]);
            acc[i][2] = fma2(wv, a2, acc[i][2]);
            acc[i][3] = fma2(wv, a3, acc[i][3]);
        }
    }
    #pragma unroll
    for (int i = 0; i < 6; i++) {
        int oc = ty*6 + i;
        float* ob = out + ((size_t)(b*CDIM + oc)*512 + h)*512 + wb;
        float2 f0 = unpack2(acc[i][0]), f1 = unpack2(acc[i][1]);
        float2 f2 = unpack2(acc[i][2]), f3 = unpack2(acc[i][3]);
        float4 o0; o0.x = f0.x; o0.y = f0.y; o0.z = f1.x; o0.w = f1.y;
        float4 o1; o1.x = f2.x; o1.y = f2.y; o1.z = f3.x; o1.w = f3.y;
        *(float4*)&ob[4*tx]       = o0;
        *(float4*)&ob[128 + 4*tx] = o1;
    }
}

extern "C" void kernel_launch(void* const* d_in, const int* in_sizes, int n_in,
                              void* d_out, int out_size) {
    const float* x     = (const float*)d_in[0];
    const float* qkvw  = (const float*)d_in[1];
    const float* dww   = (const float*)d_in[2];
    const float* projw = (const float*)d_in[3];
    const float* temp  = (const float*)d_in[4];
    float* out = (float*)d_out;

    int gram_smem = 4 * GSTG * 4;                       // 52224 B
    cudaFuncSetAttribute(k_pw,   cudaFuncAttributeMaxDynamicSharedMemorySize, PW_SMEM);
    cudaFuncSetAttribute(k_gram, cudaFuncAttributeMaxDynamicSharedMemorySize, gram_smem);
    cudaFuncSetAttribute(k_av,   cudaFuncAttributeMaxDynamicSharedMemorySize, AV_SMEM);
    cudaFuncSetAttribute(k_proj, cudaFuncAttributeMaxDynamicSharedMemorySize, PROJ_SMEM);

    k_zero<<<576, 256>>>();
    k_pw  <<<dim3(HW/256, BATCH), 256, PW_SMEM>>>(x, qkvw);
    k_dw  <<<BATCH*QC*64, 256>>>(dww);
    k_gram<<<dim3(32, NBH), 256, gram_smem>>>();
    k_soft<<<192, 256>>>(temp);
    k_av  <<<dim3(NPIX/128, NBH), 256, AV_SMEM>>>();
    k_proj<<<dim3(2, 512, BATCH), dim3(32, 8), PROJ_SMEM>>>(projw, out);
}